// round 15
// baseline (speedup 1.0000x reference)
#include <cuda_runtime.h>
#include <stdint.h>
#include <math.h>

// Problem constants
#define T_TOK 32768      // 8 * 4096 tokens
#define HDIM  1024
#define NEXP  64
#define TOPK  8
#define NB    8
#define SEQ   4096
#define TILE  64         // tokens per CTA
#define KT    64         // k-tile width
#define KC    256        // k-panel width (accumulator restart) — FROZEN numerics
#define ASTR  68         // A smem row stride (multiple of 4 -> aligned LDS.128)
#define ASZ   (TILE * ASTR)
#define BSZ   (KT * NEXP)    // B stage: k-major [k][64 experts], half-swapped

__device__ int   g_cnt [NB * NEXP];
__device__ float g_ssum[NB * NEXP];
__device__ float g_wT  [HDIM * NEXP];   // g_wT[k][e] = w[e][k]

__global__ void prep_kernel(const float* __restrict__ w) {
    int i = blockIdx.x * 256 + threadIdx.x;   // 0..65535
    int k = i >> 6, e = i & 63;
    g_wT[i] = w[e * HDIM + k];
    if (i < NB * NEXP) { g_cnt[i] = 0; g_ssum[i] = 0.0f; }
}

__device__ __forceinline__ void cp16(unsigned int dst, const float* src) {
    asm volatile("cp.async.ca.shared.global [%0], [%1], 16;\n" :: "r"(dst), "l"(src));
}
__device__ __forceinline__ void cp_commit() {
    asm volatile("cp.async.commit_group;\n");
}

// f32x2 helpers — each half is a standard fp32 FMA (chain order preserved).
#define PACK2(d, lo, hi) \
    asm("mov.b64 %0, {%1, %2};" : "=l"(d) : "r"(__float_as_uint(lo)), "r"(__float_as_uint(hi)))
#define UNPACK2(lo, hi, v) \
    do { unsigned int _ul, _uh; \
         asm("mov.b64 {%0, %1}, %2;" : "=r"(_ul), "=r"(_uh) : "l"(v)); \
         lo = __uint_as_float(_ul); hi = __uint_as_float(_uh); } while (0)
#define FMA2(d, a, b) \
    asm("fma.rn.f32x2 %0, %1, %2, %0;" : "+l"(d) : "l"(a), "l"(b))

// One CTA: 64 tokens x 64 experts, 64 threads, 8 tok x 8 exp per thread.
// Thread tokens are stride-8 (r0, r0+8, ..): warp lanes' A rows land on
// distinct smem banks -> 1-phase A-LDS.128. B k-major + half-swap -> 1-phase.
// Panel folds to smem every KC=256; FROZEN numerics throughout.
__global__ __launch_bounds__(64) void gate_kernel(
    const float* __restrict__ hs,   // [T_TOK, HDIM]
    float* __restrict__ out)        // flat f32: [idx | weights | aux | counts]
{
    __shared__ float a_s[2][ASZ];          // token tiles, row-major, stride 68
    __shared__ float b_s[2][BSZ];          // weight tiles, k-major, half-swapped
    __shared__ float s_p[TILE][NEXP + 1];  // panel totals -> logits -> probs
    __shared__ int   s_hist[NEXP];

    const int tid   = threadIdx.x;
    const int tBase = blockIdx.x * TILE;
    const int b     = blockIdx.x >> 6;     // 64 CTAs per batch

    s_hist[tid] = 0;                       // 64 threads cover NEXP

    const int r0 = tid >> 3;               // token base; rows r0 + 8j
    const int m  = tid & 7;                // expert-block index
    const int c0 = m * 8;                  // 8 experts
    const int off1 = 8 * m + ((m >= 4) ? 4 : 0);  // experts c0..c0+3 (swapped)
    const int off2 = 8 * m + ((m >= 4) ? 0 : 4);  // experts c0+4..c0+7

    // Zero own output cells (panel folds accumulate; 0 + x == x exactly).
#pragma unroll
    for (int j = 0; j < 8; ++j)
#pragma unroll
        for (int e = 0; e < 8; ++e) s_p[r0 + 8 * j][c0 + e] = 0.0f;

    unsigned long long accp[8][4];         // [token j][expert-pair]
#pragma unroll
    for (int j = 0; j < 8; ++j)
#pragma unroll
        for (int p = 0; p < 4; ++p) accp[j][p] = 0ull;

    // Loader: slot t covers rows row0 + 4t (t=0..15); sg fixed per thread.
    const int row0 = tid >> 4;             // 0..3
    const int sg   = tid & 15;             // 16B segment within row
    const int bm = sg >> 1, bh = sg & 1;
    const int ph = (bm >= 4) ? (1 - bh) : bh;       // B half-swap
    const int saBase = row0 * ASTR + 4 * sg;        // step 4*ASTR per t
    const int gaBase = row0 * HDIM + 4 * sg;        // step 4*HDIM per t
    const int sbBase = row0 * NEXP + bm * 8 + ph * 4;  // step 4*NEXP per t
    const int gbBase = row0 * NEXP + 4 * sg;        // step 4*NEXP per t

    unsigned int aB = (unsigned int)__cvta_generic_to_shared(&a_s[0][0]);
    unsigned int bB = (unsigned int)__cvta_generic_to_shared(&b_s[0][0]);
    const float* hsT = hs + (size_t)tBase * HDIM;

    // Prologue: async-load tile 0 into stage 0.
#pragma unroll
    for (int t = 0; t < 16; ++t) {
        cp16(aB + 4 * (saBase + t * 4 * ASTR), hsT  + gaBase + t * 4 * HDIM);
        cp16(bB + 4 * (sbBase + t * 4 * NEXP), g_wT + gbBase + t * 4 * NEXP);
    }
    cp_commit();

    const int NT = HDIM / KT;              // 16 tiles
    for (int tt = 0; tt < NT; ++tt) {
        const int st = tt & 1;
        if (tt + 1 < NT) {
            const int ns = (tt + 1) & 1;
            const int kn = (tt + 1) * KT;
#pragma unroll
            for (int t = 0; t < 16; ++t) {
                cp16(aB + 4 * (ns * ASZ + saBase + t * 4 * ASTR),
                     hsT + gaBase + t * 4 * HDIM + kn);
                cp16(bB + 4 * (ns * BSZ + sbBase + t * 4 * NEXP),
                     g_wT + (size_t)kn * NEXP + gbBase + t * 4 * NEXP);
            }
            cp_commit();
            asm volatile("cp.async.wait_group 1;\n");
        } else {
            asm volatile("cp.async.wait_group 0;\n");
        }
        __syncthreads();

        const float* aS = a_s[st];
        const float* bS = b_s[st];

        // Per k4: 8 A-LDS.128 (1 phase), 8 B-LDS.128 (1 phase), 32 dup-packs,
        // 128 FMA2. Chain per (tok,exp) strictly k-ascending — FROZEN.
#pragma unroll 2
        for (int k4 = 0; k4 < KT; k4 += 4) {
            float4 aR[8];
#pragma unroll
            for (int j = 0; j < 8; ++j)
                aR[j] = *reinterpret_cast<const float4*>(aS + (r0 + 8 * j) * ASTR + k4);
#pragma unroll
            for (int i = 0; i < 4; ++i) {
                const float* bk = bS + (k4 + i) * NEXP;
                ulonglong2 B01 = *reinterpret_cast<const ulonglong2*>(bk + off1);
                ulonglong2 B23 = *reinterpret_cast<const ulonglong2*>(bk + off2);
#pragma unroll
                for (int j = 0; j < 8; ++j) {
                    float av = (i == 0) ? aR[j].x : (i == 1) ? aR[j].y
                             : (i == 2) ? aR[j].z : aR[j].w;
                    unsigned long long aj;
                    PACK2(aj, av, av);
                    FMA2(accp[j][0], aj, B01.x); FMA2(accp[j][1], aj, B01.y);
                    FMA2(accp[j][2], aj, B23.x); FMA2(accp[j][3], aj, B23.y);
                }
            }
        }

        // End of KC-panel (every 4 tiles): fold into smem totals in order.
        if ((((tt + 1) * KT) & (KC - 1)) == 0) {
#pragma unroll
            for (int j = 0; j < 8; ++j)
#pragma unroll
                for (int p = 0; p < 4; ++p) {
                    float lo, hi;
                    UNPACK2(lo, hi, accp[j][p]);
                    s_p[r0 + 8 * j][c0 + 2 * p]     += lo;
                    s_p[r0 + 8 * j][c0 + 2 * p + 1] += hi;
                    accp[j][p] = 0ull;
                }
        }
        __syncthreads();
    }
    __syncthreads();

    // ---- Epilogue: one token per thread (exact R4 form — FROZEN) ----
    {
        const int t = tid;
        float mx = -1e30f;
#pragma unroll 8
        for (int e = 0; e < NEXP; ++e) mx = fmaxf(mx, s_p[t][e]);
        float sum = 0.0f;
#pragma unroll 8
        for (int e = 0; e < NEXP; ++e) {
            float p = (float)exp((double)(s_p[t][e] - mx));
            s_p[t][e] = p;
            sum += p;
        }
        float inv = (float)(1.0 / (double)sum);
#pragma unroll 8
        for (int e = 0; e < NEXP; ++e) s_p[t][e] *= inv;

        // top-8, descending, lowest index first on exact ties (lax.top_k)
        int   idx[TOPK];
        float wk [TOPK];
        float wsum = 0.0f;
#pragma unroll
        for (int s = 0; s < TOPK; ++s) {
            float best = -1.0f; int bi = 0;
            for (int e = 0; e < NEXP; ++e) {
                float v = s_p[t][e];
                if (v > best) { best = v; bi = e; }
            }
            idx[s] = bi; wk[s] = best; wsum += best;
            s_p[t][bi] = -1.0f;
        }
#pragma unroll
        for (int s = 0; s < TOPK; ++s) s_p[t][idx[s]] = wk[s];  // restore

        float inv2 = (float)(1.0 / ((double)wsum + 1e-20));
        size_t gt = (size_t)tBase + t;
#pragma unroll
        for (int s = 0; s < TOPK; ++s) {
            out[gt * TOPK + s] = (float)idx[s];
            out[(size_t)T_TOK * TOPK + gt * TOPK + s] = wk[s] * inv2;
            atomicAdd(&s_hist[idx[s]], 1);
        }
    }
    __syncthreads();

    {
        const int e = tid;      // 64 threads cover NEXP
        float cs = 0.0f;
        for (int t2 = 0; t2 < TILE; ++t2) cs += s_p[t2][e];
        atomicAdd(&g_ssum[b * NEXP + e], cs);
        atomicAdd(&g_cnt [b * NEXP + e], s_hist[e]);
    }
}

// aux = ALPHA * mean_b sum_e [cnt(b,e) * NEXP/(SEQ*TOPK)] * [ssum(b,e)/SEQ]
__global__ void final_kernel(float* __restrict__ out) {
    __shared__ float red[NEXP];
    int e = threadIdx.x;          // 64 threads
    int c = 0; float partial = 0.0f;
#pragma unroll
    for (int b = 0; b < NB; ++b) {
        int cb = g_cnt[b * NEXP + e];
        c += cb;
        partial += (float)cb * g_ssum[b * NEXP + e];
    }
    out[(size_t)T_TOK * 2 * TOPK + 1 + e] = (float)c;  // expert_counts
    red[e] = partial;
    __syncthreads();
    if (e == 0) {
        float s = 0.0f;
        for (int i = 0; i < NEXP; ++i) s += red[i];
        float aux = 0.01f * ((float)NEXP / (float)(SEQ * TOPK))
                          * (1.0f / (float)SEQ) * (1.0f / (float)NB) * s;
        out[(size_t)T_TOK * 2 * TOPK] = aux;           // aux_loss
    }
}

extern "C" void kernel_launch(void* const* d_in, const int* in_sizes, int n_in,
                              void* d_out, int out_size) {
    const float* hs = (const float*)d_in[0];   // hidden_states [8,4096,1024] f32
    const float* w  = (const float*)d_in[1];   // weight [64,1024] f32
    float* out = (float*)d_out;

    prep_kernel <<<HDIM * NEXP / 256, 256>>>(w);
    gate_kernel <<<T_TOK / TILE, 64>>>(hs, out);
    final_kernel<<<1, NEXP>>>(out);
}

// round 16
// speedup vs baseline: 1.1562x; 1.1562x over previous
#include <cuda_runtime.h>
#include <stdint.h>
#include <math.h>

// Problem constants
#define T_TOK 32768      // 8 * 4096 tokens
#define HDIM  1024
#define NEXP  64
#define TOPK  8
#define NB    8
#define SEQ   4096
#define TILE  64         // tokens per CTA
#define KT    64         // k-tile width
#define KC    256        // k-panel width (accumulator restart) — FROZEN numerics
#define ASTR  68         // A smem row stride
#define ASZ   (TILE * ASTR)
#define BSZ   (KT * NEXP)    // B stage: k-major [k][64 experts], half-swapped

__device__ int   g_cnt [NB * NEXP];
__device__ float g_ssum[NB * NEXP];
__device__ float g_wT  [HDIM * NEXP];   // g_wT[k][e] = w[e][k]

__global__ void prep_kernel(const float* __restrict__ w) {
    int i = blockIdx.x * 256 + threadIdx.x;   // 0..65535
    int k = i >> 6, e = i & 63;
    g_wT[i] = w[e * HDIM + k];
    if (i < NB * NEXP) { g_cnt[i] = 0; g_ssum[i] = 0.0f; }
}

__device__ __forceinline__ void cp16(unsigned int dst, const float* src) {
    asm volatile("cp.async.ca.shared.global [%0], [%1], 16;\n" :: "r"(dst), "l"(src));
}
__device__ __forceinline__ void cp_commit() {
    asm volatile("cp.async.commit_group;\n");
}

// f32x2 helpers — each half is a standard fp32 FMA (chain order preserved).
#define PACK2(d, lo, hi) \
    asm("mov.b64 %0, {%1, %2};" : "=l"(d) : "r"(__float_as_uint(lo)), "r"(__float_as_uint(hi)))
#define UNPACK2(lo, hi, v) \
    do { unsigned int _ul, _uh; \
         asm("mov.b64 {%0, %1}, %2;" : "=r"(_ul), "=r"(_uh) : "l"(v)); \
         lo = __uint_as_float(_ul); hi = __uint_as_float(_uh); } while (0)
#define FMA2(d, a, b) \
    asm("fma.rn.f32x2 %0, %1, %2, %0;" : "+l"(d) : "l"(a), "l"(b))

// One CTA: 64 tokens x 64 experts, 128 threads, 4 tok x 8 exp per thread.
// Tokens are stride-16 per thread (r0 + 16j): the 4 distinct A rows per warp
// land on distinct 16B banks -> 1-phase A-LDS.128 (R14 was 2-phase).
// B k-major + half-swap -> 1-phase. Panel folds to smem every KC=256.
__global__ __launch_bounds__(128) void gate_kernel(
    const float* __restrict__ hs,   // [T_TOK, HDIM]
    float* __restrict__ out)        // flat f32: [idx | weights | aux | counts]
{
    __shared__ float a_s[2][ASZ];          // token tiles, row-major, stride 68
    __shared__ float b_s[2][BSZ];          // weight tiles, k-major, half-swapped
    __shared__ float s_p[TILE][NEXP + 1];  // panel totals -> logits -> probs
    __shared__ float s_mx[2][TILE];
    __shared__ int   s_hist[NEXP];

    const int tid   = threadIdx.x;
    const int tBase = blockIdx.x * TILE;
    const int b     = blockIdx.x >> 6;     // 64 CTAs per batch

    if (tid < NEXP) s_hist[tid] = 0;

    const int r0 = tid >> 3;               // token base (0..15); rows r0 + 16j
    const int m  = tid & 7;                // expert-block index
    const int c0 = m * 8;                  // 8 experts
    const int off1 = 8 * m + ((m >= 4) ? 4 : 0);  // experts c0..c0+3 (swapped)
    const int off2 = 8 * m + ((m >= 4) ? 0 : 4);  // experts c0+4..c0+7

    // Zero own output cells (panel folds accumulate; 0 + x == x exactly).
#pragma unroll
    for (int j = 0; j < 4; ++j)
#pragma unroll
        for (int e = 0; e < 8; ++e) s_p[r0 + 16 * j][c0 + e] = 0.0f;

    unsigned long long accp[4][4];         // [token j][expert-pair]
#pragma unroll
    for (int j = 0; j < 4; ++j)
#pragma unroll
        for (int p = 0; p < 4; ++p) accp[j][p] = 0ull;

    // Loader slots: A 1024 float4 / 128 thr = 8; B 1024 / 128 = 8.
    int saOff[8], gaOff[8], sbOff[8], gbOff[8];
#pragma unroll
    for (int t = 0; t < 8; ++t) {
        int idx = tid + t * 128;           // 0..1023
        int row = idx >> 4;                // 0..63
        int sg  = idx & 15;                // 16B segment index
        saOff[t] = row * ASTR + (sg << 2);
        gaOff[t] = row * HDIM + (sg << 2);
        int bm = sg >> 1, bh = sg & 1;
        int ph = (bm >= 4) ? (1 - bh) : bh;          // half-swap for banks
        sbOff[t] = row * NEXP + bm * 8 + ph * 4;     // row = k
        gbOff[t] = row * NEXP + (sg << 2);
    }

    unsigned int aBase = (unsigned int)__cvta_generic_to_shared(&a_s[0][0]);
    unsigned int bBase = (unsigned int)__cvta_generic_to_shared(&b_s[0][0]);

#pragma unroll
    for (int t = 0; t < 8; ++t) {
        cp16(aBase + 4 * saOff[t], hs + (size_t)tBase * HDIM + gaOff[t]);
        cp16(bBase + 4 * sbOff[t], g_wT + gbOff[t]);
    }
    cp_commit();

    const int NT = HDIM / KT;              // 16 tiles
    for (int tt = 0; tt < NT; ++tt) {
        const int st = tt & 1;
        if (tt + 1 < NT) {
            const int ns = (tt + 1) & 1;
            const int kn = (tt + 1) * KT;
#pragma unroll
            for (int t = 0; t < 8; ++t) {
                cp16(aBase + 4 * (ns * ASZ + saOff[t]),
                     hs + (size_t)tBase * HDIM + gaOff[t] + kn);
                cp16(bBase + 4 * (ns * BSZ + sbOff[t]),
                     g_wT + (size_t)kn * NEXP + gbOff[t]);
            }
            cp_commit();
            asm volatile("cp.async.wait_group 1;\n");
        } else {
            asm volatile("cp.async.wait_group 0;\n");
        }
        __syncthreads();

        const float* aS = a_s[st];
        const float* bS = b_s[st];

        // Per k: 2 B-LDS.128 (1 phase), 4 A-dup MOV, 16 FMA2.
        // Chain per (tok,exp) strictly k-ascending — FROZEN.
#pragma unroll 2
        for (int k4 = 0; k4 < KT; k4 += 4) {
            float4 aR0 = *reinterpret_cast<const float4*>(aS + (r0 +  0) * ASTR + k4);
            float4 aR1 = *reinterpret_cast<const float4*>(aS + (r0 + 16) * ASTR + k4);
            float4 aR2 = *reinterpret_cast<const float4*>(aS + (r0 + 32) * ASTR + k4);
            float4 aR3 = *reinterpret_cast<const float4*>(aS + (r0 + 48) * ASTR + k4);
#pragma unroll
            for (int i = 0; i < 4; ++i) {
                const float* bk = bS + (k4 + i) * NEXP;
                ulonglong2 B01 = *reinterpret_cast<const ulonglong2*>(bk + off1);
                ulonglong2 B23 = *reinterpret_cast<const ulonglong2*>(bk + off2);
                float av0 = (i == 0) ? aR0.x : (i == 1) ? aR0.y : (i == 2) ? aR0.z : aR0.w;
                float av1 = (i == 0) ? aR1.x : (i == 1) ? aR1.y : (i == 2) ? aR1.z : aR1.w;
                float av2 = (i == 0) ? aR2.x : (i == 1) ? aR2.y : (i == 2) ? aR2.z : aR2.w;
                float av3 = (i == 0) ? aR3.x : (i == 1) ? aR3.y : (i == 2) ? aR3.z : aR3.w;
                unsigned long long a0, a1, a2, a3;
                PACK2(a0, av0, av0); PACK2(a1, av1, av1);
                PACK2(a2, av2, av2); PACK2(a3, av3, av3);
                FMA2(accp[0][0], a0, B01.x); FMA2(accp[0][1], a0, B01.y);
                FMA2(accp[0][2], a0, B23.x); FMA2(accp[0][3], a0, B23.y);
                FMA2(accp[1][0], a1, B01.x); FMA2(accp[1][1], a1, B01.y);
                FMA2(accp[1][2], a1, B23.x); FMA2(accp[1][3], a1, B23.y);
                FMA2(accp[2][0], a2, B01.x); FMA2(accp[2][1], a2, B01.y);
                FMA2(accp[2][2], a2, B23.x); FMA2(accp[2][3], a2, B23.y);
                FMA2(accp[3][0], a3, B01.x); FMA2(accp[3][1], a3, B01.y);
                FMA2(accp[3][2], a3, B23.x); FMA2(accp[3][3], a3, B23.y);
            }
        }

        // End of KC-panel (every 4 tiles): fold into smem totals in order.
        if ((((tt + 1) * KT) & (KC - 1)) == 0) {
#pragma unroll
            for (int j = 0; j < 4; ++j)
#pragma unroll
                for (int p = 0; p < 4; ++p) {
                    float lo, hi;
                    UNPACK2(lo, hi, accp[j][p]);
                    s_p[r0 + 16 * j][c0 + 2 * p]     += lo;
                    s_p[r0 + 16 * j][c0 + 2 * p + 1] += hi;
                    accp[j][p] = 0ull;
                }
        }
        __syncthreads();
    }
    __syncthreads();

    // ---- Epilogue (same math as R11/R14; 128-thread mapping) ----
    const int et = tid & 63;     // token
    const int eq = tid >> 6;     // half (32 experts)
    {
        float mx = -1e30f;
#pragma unroll
        for (int e = eq * 32; e < eq * 32 + 32; ++e) mx = fmaxf(mx, s_p[et][e]);
        s_mx[eq][et] = mx;
    }
    __syncthreads();
    {
        float mx = fmaxf(s_mx[0][et], s_mx[1][et]);
        // exp in fp64 -> correctly-rounded fp32 scores (FROZEN)
#pragma unroll
        for (int e = eq * 32; e < eq * 32 + 32; ++e)
            s_p[et][e] = (float)exp((double)(s_p[et][e] - mx));
    }
    __syncthreads();

    if (tid < TILE) {
        const int t = tid;
        float sum = 0.0f;
#pragma unroll 8
        for (int e = 0; e < NEXP; ++e) sum += s_p[t][e];   // in index order
        float inv = (float)(1.0 / (double)sum);
#pragma unroll 8
        for (int e = 0; e < NEXP; ++e) s_p[t][e] *= inv;

        // top-8, descending, lowest index first on exact ties (lax.top_k)
        int   idx[TOPK];
        float wk [TOPK];
        float wsum = 0.0f;
#pragma unroll
        for (int s = 0; s < TOPK; ++s) {
            float best = -1.0f; int bi = 0;
            for (int e = 0; e < NEXP; ++e) {
                float v = s_p[t][e];
                if (v > best) { best = v; bi = e; }
            }
            idx[s] = bi; wk[s] = best; wsum += best;
            s_p[t][bi] = -1.0f;
        }
#pragma unroll
        for (int s = 0; s < TOPK; ++s) s_p[t][idx[s]] = wk[s];  // restore

        float inv2 = (float)(1.0 / ((double)wsum + 1e-20));
        size_t gt = (size_t)tBase + t;
#pragma unroll
        for (int s = 0; s < TOPK; ++s) {
            out[gt * TOPK + s] = (float)idx[s];
            out[(size_t)T_TOK * TOPK + gt * TOPK + s] = wk[s] * inv2;
            atomicAdd(&s_hist[idx[s]], 1);
        }
    }
    __syncthreads();

    if (tid < NEXP) {
        const int e = tid;
        float cs = 0.0f;
        for (int t2 = 0; t2 < TILE; ++t2) cs += s_p[t2][e];
        atomicAdd(&g_ssum[b * NEXP + e], cs);
        atomicAdd(&g_cnt [b * NEXP + e], s_hist[e]);
    }
}

// aux = ALPHA * mean_b sum_e [cnt(b,e) * NEXP/(SEQ*TOPK)] * [ssum(b,e)/SEQ]
__global__ void final_kernel(float* __restrict__ out) {
    __shared__ float red[NEXP];
    int e = threadIdx.x;          // 64 threads
    int c = 0; float partial = 0.0f;
#pragma unroll
    for (int b = 0; b < NB; ++b) {
        int cb = g_cnt[b * NEXP + e];
        c += cb;
        partial += (float)cb * g_ssum[b * NEXP + e];
    }
    out[(size_t)T_TOK * 2 * TOPK + 1 + e] = (float)c;  // expert_counts
    red[e] = partial;
    __syncthreads();
    if (e == 0) {
        float s = 0.0f;
        for (int i = 0; i < NEXP; ++i) s += red[i];
        float aux = 0.01f * ((float)NEXP / (float)(SEQ * TOPK))
                          * (1.0f / (float)SEQ) * (1.0f / (float)NB) * s;
        out[(size_t)T_TOK * 2 * TOPK] = aux;           // aux_loss
    }
}

extern "C" void kernel_launch(void* const* d_in, const int* in_sizes, int n_in,
                              void* d_out, int out_size) {
    const float* hs = (const float*)d_in[0];   // hidden_states [8,4096,1024] f32
    const float* w  = (const float*)d_in[1];   // weight [64,1024] f32
    float* out = (float*)d_out;

    prep_kernel <<<HDIM * NEXP / 256, 256>>>(w);
    gate_kernel <<<T_TOK / TILE, 128>>>(hs, out);
    final_kernel<<<1, NEXP>>>(out);
}